// round 3
// baseline (speedup 1.0000x reference)
#include <cuda_runtime.h>

// ---------------- problem constants ----------------
constexpr int BATCH = 2;
constexpr int NTOK  = 2048;
constexpr int CDIM  = 1024;
constexpr int HEADS = 16;
constexpr int HDIM  = 64;
constexpr int MROWS = BATCH * NTOK;     // 4096
constexpr int QKVC  = 3 * CDIM;         // 3072

// ---------------- scratch (device globals, no allocation) ----------------
__device__ float g_Weff_qkv[QKVC * CDIM];   // 12 MB
__device__ float g_Weff_p[CDIM * CDIM];     //  4 MB
__device__ float g_qkv[MROWS * QKVC];       // 48 MB
__device__ float g_ctx[MROWS * CDIM];       // 16 MB

// ---------------- weight fusion: Weff = W + 2 * B @ A ----------------
__device__ __forceinline__ void fuse_body(const float* __restrict__ W,
                                          const float* __restrict__ Bm,
                                          const float* __restrict__ A,
                                          float* __restrict__ Weff, int total)
{
    int idx = blockIdx.x * blockDim.x + threadIdx.x;
    if (idx >= total) return;
    int i = idx >> 10;       // / CDIM
    int j = idx & 1023;      // % CDIM
    float s = 0.f;
#pragma unroll
    for (int r = 0; r < 16; r++) s += Bm[i * 16 + r] * A[r * CDIM + j];
    Weff[idx] = W[idx] + 2.0f * s;
}

__global__ void fuse_qkv_kernel(const float* __restrict__ W, const float* __restrict__ Bm,
                                const float* __restrict__ A)
{
    fuse_body(W, Bm, A, g_Weff_qkv, QKVC * CDIM);
}

__global__ void fuse_p_kernel(const float* __restrict__ W, const float* __restrict__ Bm,
                              const float* __restrict__ A)
{
    fuse_body(W, Bm, A, g_Weff_p, CDIM * CDIM);
}

// ---------------- SGEMM: C[M,Nc] = A[M,1024] @ B[Nc,1024]^T + bias ----------------
// 128x128 tile, BK=16, 256 threads, 8x8 per thread.
__device__ __forceinline__ void sgemm_body(const float* __restrict__ A,
                                           const float* __restrict__ B,
                                           const float* __restrict__ bias,
                                           float* __restrict__ C, int Nc)
{
    constexpr int K = 1024;
    __shared__ float As[16][132];
    __shared__ float Bs[16][132];

    const int tid = threadIdx.x;
    const int tx = tid & 15, ty = tid >> 4;
    const int row0 = blockIdx.y * 128;
    const int col0 = blockIdx.x * 128;

    const float* Ab = A + (size_t)row0 * K;
    const float* Bb = B + (size_t)col0 * K;

    float acc[8][8];
#pragma unroll
    for (int i = 0; i < 8; i++)
#pragma unroll
        for (int j = 0; j < 8; j++) acc[i][j] = 0.f;

    for (int k0 = 0; k0 < K; k0 += 16) {
#pragma unroll
        for (int i = 0; i < 2; i++) {
            int idx4 = tid + i * 256;          // 0..511 float4s
            int r  = idx4 >> 2;                // tile row 0..127
            int kq = (idx4 & 3) * 4;           // k offset 0,4,8,12
            float4 va = *reinterpret_cast<const float4*>(Ab + (size_t)r * K + k0 + kq);
            As[kq + 0][r] = va.x; As[kq + 1][r] = va.y;
            As[kq + 2][r] = va.z; As[kq + 3][r] = va.w;
            float4 vb = *reinterpret_cast<const float4*>(Bb + (size_t)r * K + k0 + kq);
            Bs[kq + 0][r] = vb.x; Bs[kq + 1][r] = vb.y;
            Bs[kq + 2][r] = vb.z; Bs[kq + 3][r] = vb.w;
        }
        __syncthreads();
#pragma unroll
        for (int kk = 0; kk < 16; kk++) {
            float ar[8], br[8];
            *reinterpret_cast<float4*>(&ar[0]) = *reinterpret_cast<const float4*>(&As[kk][ty * 8]);
            *reinterpret_cast<float4*>(&ar[4]) = *reinterpret_cast<const float4*>(&As[kk][ty * 8 + 4]);
            *reinterpret_cast<float4*>(&br[0]) = *reinterpret_cast<const float4*>(&Bs[kk][tx * 8]);
            *reinterpret_cast<float4*>(&br[4]) = *reinterpret_cast<const float4*>(&Bs[kk][tx * 8 + 4]);
#pragma unroll
            for (int i = 0; i < 8; i++)
#pragma unroll
                for (int j = 0; j < 8; j++) acc[i][j] += ar[i] * br[j];
        }
        __syncthreads();
    }

#pragma unroll
    for (int i = 0; i < 8; i++) {
        int row = row0 + ty * 8 + i;
#pragma unroll
        for (int j4 = 0; j4 < 2; j4++) {
            int col = col0 + tx * 8 + j4 * 4;
            float4 bv = *reinterpret_cast<const float4*>(&bias[col]);
            float4 r;
            r.x = acc[i][j4 * 4 + 0] + bv.x;
            r.y = acc[i][j4 * 4 + 1] + bv.y;
            r.z = acc[i][j4 * 4 + 2] + bv.z;
            r.w = acc[i][j4 * 4 + 3] + bv.w;
            *reinterpret_cast<float4*>(&C[(size_t)row * Nc + col]) = r;
        }
    }
}

__global__ void __launch_bounds__(256, 2)
gemm_qkv_kernel(const float* __restrict__ x, const float* __restrict__ bias)
{
    sgemm_body(x, g_Weff_qkv, bias, g_qkv, QKVC);
}

__global__ void __launch_bounds__(256, 2)
gemm_proj_kernel(const float* __restrict__ bias, float* __restrict__ out)
{
    sgemm_body(g_ctx, g_Weff_p, bias, out, CDIM);
}

// ---------------- flash attention, fp32, BQ=BK=64, d=64 ----------------
// 256 threads: 16x16 grid, each thread owns 4 q-rows x 4 cols.
// smem: Qt[64][68] (Q^T), Ks[64][68] (K^T, reused as P^T), Vs[64][68].
// SROW=68: row stride 272 B = 17*16 -> every float4 access 16B-aligned,
// and 68 mod 32 = 4 banks rotation avoids transposed-store conflicts.
constexpr int SROW = 68;

__global__ void __launch_bounds__(256)
flash_kernel(const int* __restrict__ mask)
{
    extern __shared__ float sm[];
    float* Qt = sm;                 // [d][q]
    float* Ks = sm + 64 * SROW;     // [d][k], later P^T [k][q]
    float* Vs = sm + 2 * 64 * SROW; // [k][d]

    const int tid = threadIdx.x;
    const int tx = tid & 15, ty = tid >> 4;
    const int b = blockIdx.z, h = blockIdx.y;
    const int q0 = blockIdx.x * 64;

    // load Q tile (transposed into smem)
    const float* Qg = g_qkv + (size_t)(b * NTOK + q0) * QKVC + h * HDIM;
#pragma unroll
    for (int i = 0; i < 4; i++) {
        int idx4 = tid + i * 256;
        int r  = idx4 >> 4;          // token 0..63
        int d4 = (idx4 & 15) * 4;    // dim 0,4,...,60
        float4 v = *reinterpret_cast<const float4*>(Qg + (size_t)r * QKVC + d4);
        Qt[(d4 + 0) * SROW + r] = v.x;
        Qt[(d4 + 1) * SROW + r] = v.y;
        Qt[(d4 + 2) * SROW + r] = v.z;
        Qt[(d4 + 3) * SROW + r] = v.w;
    }

    float m_[4] = {-1e30f, -1e30f, -1e30f, -1e30f};
    float l_[4] = {0.f, 0.f, 0.f, 0.f};
    float o[4][4] = {};
    const int* mrow = mask + b * NTOK;

    for (int k0 = 0; k0 < NTOK; k0 += 64) {
        __syncthreads();   // previous PV done before overwriting Ks/Vs
        const float* Kg = g_qkv + (size_t)(b * NTOK + k0) * QKVC + CDIM + h * HDIM;
#pragma unroll
        for (int i = 0; i < 4; i++) {
            int idx4 = tid + i * 256;
            int r  = idx4 >> 4;
            int d4 = (idx4 & 15) * 4;
            float4 kv = *reinterpret_cast<const float4*>(Kg + (size_t)r * QKVC + d4);
            Ks[(d4 + 0) * SROW + r] = kv.x;
            Ks[(d4 + 1) * SROW + r] = kv.y;
            Ks[(d4 + 2) * SROW + r] = kv.z;
            Ks[(d4 + 3) * SROW + r] = kv.w;
            float4 vv = *reinterpret_cast<const float4*>(Kg + CDIM + (size_t)r * QKVC + d4);
            *reinterpret_cast<float4*>(&Vs[r * SROW + d4]) = vv;
        }
        __syncthreads();

        // S = Q K^T (outer-product over d)
        float s[4][4] = {};
#pragma unroll 8
        for (int kk = 0; kk < 64; kk++) {
            float4 a  = *reinterpret_cast<const float4*>(&Qt[kk * SROW + ty * 4]);
            float4 bb = *reinterpret_cast<const float4*>(&Ks[kk * SROW + tx * 4]);
            float ar[4] = {a.x, a.y, a.z, a.w};
            float br[4] = {bb.x, bb.y, bb.z, bb.w};
#pragma unroll
            for (int i = 0; i < 4; i++)
#pragma unroll
                for (int j = 0; j < 4; j++) s[i][j] += ar[i] * br[j];
        }

        // scale + mask
        float msk[4];
#pragma unroll
        for (int j = 0; j < 4; j++)
            msk[j] = (mrow[k0 + tx * 4 + j] == 0) ? -1e30f : 0.0f;

        // online softmax (row groups of 16 threads; xor<=8 stays in group)
#pragma unroll
        for (int i = 0; i < 4; i++) {
#pragma unroll
            for (int j = 0; j < 4; j++) s[i][j] = s[i][j] * 0.125f + msk[j];
            float pm = fmaxf(fmaxf(s[i][0], s[i][1]), fmaxf(s[i][2], s[i][3]));
#pragma unroll
            for (int off = 8; off; off >>= 1)
                pm = fmaxf(pm, __shfl_xor_sync(0xffffffffu, pm, off));
            float mn = fmaxf(m_[i], pm);
            float alpha = __expf(m_[i] - mn);
            m_[i] = mn;
            float ps = 0.f;
#pragma unroll
            for (int j = 0; j < 4; j++) {
                float p = __expf(s[i][j] - mn);
                s[i][j] = p;
                ps += p;
            }
#pragma unroll
            for (int off = 8; off; off >>= 1)
                ps += __shfl_xor_sync(0xffffffffu, ps, off);
            l_[i] = l_[i] * alpha + ps;
#pragma unroll
            for (int j = 0; j < 4; j++) o[i][j] *= alpha;
        }

        __syncthreads();   // all Ks reads done; safe to overwrite with P^T
#pragma unroll
        for (int j = 0; j < 4; j++) {
            float4 pc = make_float4(s[0][j], s[1][j], s[2][j], s[3][j]);
            *reinterpret_cast<float4*>(&Ks[(tx * 4 + j) * SROW + ty * 4]) = pc;
        }
        __syncthreads();

        // O += P V (outer-product over k)
#pragma unroll 8
        for (int kc = 0; kc < 64; kc++) {
            float4 a  = *reinterpret_cast<const float4*>(&Ks[kc * SROW + ty * 4]);
            float4 bv = *reinterpret_cast<const float4*>(&Vs[kc * SROW + tx * 4]);
            float ar[4] = {a.x, a.y, a.z, a.w};
            float br[4] = {bv.x, bv.y, bv.z, bv.w};
#pragma unroll
            for (int i = 0; i < 4; i++)
#pragma unroll
                for (int j = 0; j < 4; j++) o[i][j] += ar[i] * br[j];
        }
    }

    // normalize + write ctx in [B, N, H*d] layout (ready for proj GEMM)
#pragma unroll
    for (int i = 0; i < 4; i++) {
        float inv = 1.0f / l_[i];
        float4 r = make_float4(o[i][0] * inv, o[i][1] * inv, o[i][2] * inv, o[i][3] * inv);
        size_t row = (size_t)(b * NTOK + q0 + ty * 4 + i);
        *reinterpret_cast<float4*>(&g_ctx[row * CDIM + h * HDIM + tx * 4]) = r;
    }
}

// ---------------- launch ----------------
extern "C" void kernel_launch(void* const* d_in, const int* in_sizes, int n_in,
                              void* d_out, int out_size)
{
    (void)in_sizes; (void)n_in; (void)out_size;
    const float* x    = (const float*)d_in[0];
    const int*   mask = (const int*)d_in[1];
    const float* Wqkv = (const float*)d_in[2];
    const float* bqkv = (const float*)d_in[3];
    const float* Aqkv = (const float*)d_in[4];
    const float* Bqkv = (const float*)d_in[5];
    const float* Wp   = (const float*)d_in[6];
    const float* bp   = (const float*)d_in[7];
    const float* Ap   = (const float*)d_in[8];
    const float* Bp   = (const float*)d_in[9];
    float* out = (float*)d_out;

    // 1) fold LoRA into effective weights
    fuse_qkv_kernel<<<(QKVC * CDIM + 255) / 256, 256>>>(Wqkv, Bqkv, Aqkv);
    fuse_p_kernel<<<(CDIM * CDIM + 255) / 256, 256>>>(Wp, Bp, Ap);

    // 2) qkv = x @ Weff_qkv^T + bqkv
    gemm_qkv_kernel<<<dim3(QKVC / 128, MROWS / 128), 256>>>(x, bqkv);

    // 3) flash attention -> g_ctx
    int smem = 3 * 64 * SROW * (int)sizeof(float);   // 52224 B
    cudaFuncSetAttribute(flash_kernel, cudaFuncAttributeMaxDynamicSharedMemorySize, smem);
    flash_kernel<<<dim3(NTOK / 64, HEADS, BATCH), 256, smem>>>(mask);

    // 4) out = ctx @ Weff_p^T + bp
    gemm_proj_kernel<<<dim3(CDIM / 128, MROWS / 128), 256>>>(bp, out);
}

// round 5
// speedup vs baseline: 1.2907x; 1.2907x over previous
#include <cuda_runtime.h>
#include <cuda_bf16.h>
#include <cstdint>

// ---------------- problem constants ----------------
constexpr int BATCH = 2;
constexpr int NTOK  = 2048;
constexpr int CDIM  = 1024;
constexpr int HEADS = 16;
constexpr int HDIM  = 64;
constexpr int MROWS = BATCH * NTOK;     // 4096
constexpr int QKVC  = 3 * CDIM;         // 3072

// ---------------- scratch (device globals, no allocation) ----------------
__device__ float g_qkv[MROWS * QKVC];                 // 48 MB (f32, flash reads it)
__device__ float g_ctx[MROWS * CDIM];                 // 16 MB (f32, flash writes it)
__device__ __nv_bfloat16 g_x_hi[MROWS * CDIM];
__device__ __nv_bfloat16 g_x_lo[MROWS * CDIM];
__device__ __nv_bfloat16 g_c_hi[MROWS * CDIM];
__device__ __nv_bfloat16 g_c_lo[MROWS * CDIM];
__device__ __nv_bfloat16 g_Wq_hi[QKVC * CDIM];
__device__ __nv_bfloat16 g_Wq_lo[QKVC * CDIM];
__device__ __nv_bfloat16 g_Wp_hi[CDIM * CDIM];
__device__ __nv_bfloat16 g_Wp_lo[CDIM * CDIM];

// ---------------- helpers ----------------
__device__ __forceinline__ void split2(float v, __nv_bfloat16& h, __nv_bfloat16& l)
{
    h = __float2bfloat16_rn(v);
    l = __float2bfloat16_rn(v - __bfloat162float(h));
}

__device__ __forceinline__ uint32_t smem_u32(const void* p)
{
    uint32_t a;
    asm("{ .reg .u64 t; cvta.to.shared.u64 t, %1; cvt.u32.u64 %0, t; }" : "=r"(a) : "l"(p));
    return a;
}

__device__ __forceinline__ void cp_async16(uint32_t dst, const void* src)
{
    asm volatile("cp.async.cg.shared.global [%0], [%1], 16;" :: "r"(dst), "l"(src));
}

__device__ __forceinline__ void ldsm_x4(uint32_t& r0, uint32_t& r1, uint32_t& r2, uint32_t& r3,
                                        uint32_t addr)
{
    asm volatile("ldmatrix.sync.aligned.m8n8.x4.shared.b16 {%0,%1,%2,%3}, [%4];"
                 : "=r"(r0), "=r"(r1), "=r"(r2), "=r"(r3) : "r"(addr));
}

__device__ __forceinline__ void mma_bf16(float* c, const uint32_t* a, const uint32_t* b)
{
    asm volatile("mma.sync.aligned.m16n8k16.row.col.f32.bf16.bf16.f32 "
                 "{%0,%1,%2,%3}, {%4,%5,%6,%7}, {%8,%9}, {%0,%1,%2,%3};"
                 : "+f"(c[0]), "+f"(c[1]), "+f"(c[2]), "+f"(c[3])
                 : "r"(a[0]), "r"(a[1]), "r"(a[2]), "r"(a[3]), "r"(b[0]), "r"(b[1]));
}

// ---------------- conversion kernels ----------------
__global__ void cvt_x_kernel(const float* __restrict__ x)
{
    int i = blockIdx.x * blockDim.x + threadIdx.x;
    if (i < MROWS * CDIM) split2(x[i], g_x_hi[i], g_x_lo[i]);
}

__global__ void cvt_ctx_kernel()
{
    int i = blockIdx.x * blockDim.x + threadIdx.x;
    if (i < MROWS * CDIM) split2(g_ctx[i], g_c_hi[i], g_c_lo[i]);
}

// ---------------- weight fusion + split: Weff = W + 2 * B @ A ----------------
__device__ __forceinline__ void fuse_body(const float* __restrict__ W,
                                          const float* __restrict__ Bm,
                                          const float* __restrict__ A,
                                          __nv_bfloat16* __restrict__ Whi,
                                          __nv_bfloat16* __restrict__ Wlo, int total)
{
    int idx = blockIdx.x * blockDim.x + threadIdx.x;
    if (idx >= total) return;
    int i = idx >> 10;
    int j = idx & 1023;
    float s = 0.f;
#pragma unroll
    for (int r = 0; r < 16; r++) s += Bm[i * 16 + r] * A[r * CDIM + j];
    split2(W[idx] + 2.0f * s, Whi[idx], Wlo[idx]);
}

__global__ void fuse_qkv_kernel(const float* __restrict__ W, const float* __restrict__ Bm,
                                const float* __restrict__ A)
{
    fuse_body(W, Bm, A, g_Wq_hi, g_Wq_lo, QKVC * CDIM);
}

__global__ void fuse_p_kernel(const float* __restrict__ W, const float* __restrict__ Bm,
                              const float* __restrict__ A)
{
    fuse_body(W, Bm, A, g_Wp_hi, g_Wp_lo, CDIM * CDIM);
}

// ---------------- HMMA GEMM: C[M,Nc] = Ahl[M,1024] @ Bhl[Nc,1024]^T + bias ----------
// 128x128 tile, 256 threads (8 warps as 2x4), 64x32 per warp.
// K-chunk = 32 bf16, double buffered cp.async.
// smem per array: 128 rows x 80 B (64 B data + 16 B pad -> ldmatrix conflict-free).
constexpr int GM_RS    = 80;                 // row stride bytes
constexpr int GM_ARR   = 128 * GM_RS;        // 10240
constexpr int GM_STAGE = 4 * GM_ARR;         // 40960 (Ahi|Alo|Bhi|Blo)
constexpr int GM_SMEM  = 2 * GM_STAGE;       // 81920
constexpr int KCH      = 32;
constexpr int NCHUNK   = 1024 / KCH;         // 32

__device__ __forceinline__ void gm_load_chunk(uint32_t su, int tid,
                                              const __nv_bfloat16* const* srcs, int c)
{
    uint32_t stage = su + (uint32_t)(c & 1) * GM_STAGE;
    int k0 = c * KCH;
#pragma unroll
    for (int i = 0; i < 8; i++) {
        int g = i * 256 + tid;     // 0..2047
        int t = g >> 9;            // array 0..3
        int e = g & 511;
        int r = e >> 2;            // row 0..127
        int c16 = e & 3;           // 16B chunk in row
        cp_async16(stage + t * GM_ARR + r * GM_RS + c16 * 16,
                   srcs[t] + (size_t)r * 1024 + k0 + c16 * 8);
    }
    asm volatile("cp.async.commit_group;");
}

__device__ __forceinline__ void mma_gemm_body(const __nv_bfloat16* __restrict__ Ahi,
                                              const __nv_bfloat16* __restrict__ Alo,
                                              const __nv_bfloat16* __restrict__ Bhi,
                                              const __nv_bfloat16* __restrict__ Blo,
                                              const float* __restrict__ bias,
                                              float* __restrict__ C, int Nc)
{
    extern __shared__ char smem[];
    const uint32_t su = smem_u32(smem);
    const int tid = threadIdx.x;
    const int wid = tid >> 5, lane = tid & 31;
    const int warp_m = wid >> 2, warp_n = wid & 3;
    const int row0 = blockIdx.y * 128;
    const int col0 = blockIdx.x * 128;

    const __nv_bfloat16* srcs[4] = {
        Ahi + (size_t)row0 * 1024, Alo + (size_t)row0 * 1024,
        Bhi + (size_t)col0 * 1024, Blo + (size_t)col0 * 1024 };

    float acc[4][4][4];
#pragma unroll
    for (int mt = 0; mt < 4; mt++)
#pragma unroll
        for (int nt = 0; nt < 4; nt++)
#pragma unroll
            for (int f = 0; f < 4; f++) acc[mt][nt][f] = 0.f;

    gm_load_chunk(su, tid, srcs, 0);

    // ldmatrix per-thread address components
    // A x4: t0-7 rows 0-7 kb0 | t8-15 rows 8-15 kb0 | t16-23 rows 0-7 kb16 | t24-31 rows 8-15 kb16
    const int a_row = warp_m * 64 + (lane & 15);
    const int a_kb  = (lane >> 4) << 4;
    // B x4: t0-7 n0-7 kb0 | t8-15 n0-7 kb16 | t16-23 n8-15 kb0 | t24-31 n8-15 kb16
    const int b_row = warp_n * 32 + ((lane & 7) | ((lane & 16) >> 1));
    const int b_kb  = (lane & 8) << 1;

    for (int c = 0; c < NCHUNK; c++) {
        if (c + 1 < NCHUNK) {
            __syncthreads();                         // all warps done with chunk c-1's stage
            gm_load_chunk(su, tid, srcs, c + 1);
            asm volatile("cp.async.wait_group 1;" ::: "memory");   // chunk c ready
        } else {
            asm volatile("cp.async.wait_group 0;" ::: "memory");
        }
        __syncthreads();

        const uint32_t stage = su + (uint32_t)(c & 1) * GM_STAGE;
#pragma unroll
        for (int ks = 0; ks < 2; ks++) {
            const uint32_t koff = ks * 32;           // 16 bf16 = 32 B

            uint32_t ah[4][4], al[4][4];
#pragma unroll
            for (int mt = 0; mt < 4; mt++) {
                uint32_t base = (uint32_t)((a_row + mt * 16) * GM_RS + a_kb + koff);
                ldsm_x4(ah[mt][0], ah[mt][1], ah[mt][2], ah[mt][3], stage + 0 * GM_ARR + base);
                ldsm_x4(al[mt][0], al[mt][1], al[mt][2], al[mt][3], stage + 1 * GM_ARR + base);
            }
            uint32_t bh[4][2], bl[4][2];
#pragma unroll
            for (int np = 0; np < 2; np++) {
                uint32_t base = (uint32_t)((b_row + np * 16) * GM_RS + b_kb + koff);
                uint32_t r0, r1, r2, r3;
                ldsm_x4(r0, r1, r2, r3, stage + 2 * GM_ARR + base);
                bh[np * 2][0] = r0; bh[np * 2][1] = r1;
                bh[np * 2 + 1][0] = r2; bh[np * 2 + 1][1] = r3;
                ldsm_x4(r0, r1, r2, r3, stage + 3 * GM_ARR + base);
                bl[np * 2][0] = r0; bl[np * 2][1] = r1;
                bl[np * 2 + 1][0] = r2; bl[np * 2 + 1][1] = r3;
            }
#pragma unroll
            for (int mt = 0; mt < 4; mt++)
#pragma unroll
                for (int nt = 0; nt < 4; nt++) {
                    mma_bf16(acc[mt][nt], ah[mt], bh[nt]);   // hi*hi
                    mma_bf16(acc[mt][nt], al[mt], bh[nt]);   // lo*hi
                    mma_bf16(acc[mt][nt], ah[mt], bl[nt]);   // hi*lo
                }
        }
    }

    // epilogue: c0,c1 -> row lane/4; c2,c3 -> row lane/4+8; cols (lane%4)*2,+1
#pragma unroll
    for (int mt = 0; mt < 4; mt++) {
        int rg = row0 + warp_m * 64 + mt * 16 + (lane >> 2);
#pragma unroll
        for (int nt = 0; nt < 4; nt++) {
            int cg = col0 + warp_n * 32 + nt * 8 + (lane & 3) * 2;
            float b0 = bias[cg], b1 = bias[cg + 1];
            float2 v0 = make_float2(acc[mt][nt][0] + b0, acc[mt][nt][1] + b1);
            float2 v1 = make_float2(acc[mt][nt][2] + b0, acc[mt][nt][3] + b1);
            *reinterpret_cast<float2*>(&C[(size_t)rg * Nc + cg]) = v0;
            *reinterpret_cast<float2*>(&C[(size_t)(rg + 8) * Nc + cg]) = v1;
        }
    }
}

__global__ void __launch_bounds__(256, 1)
mma_gemm_qkv(const float* __restrict__ bias)
{
    mma_gemm_body(g_x_hi, g_x_lo, g_Wq_hi, g_Wq_lo, bias, g_qkv, QKVC);
}

__global__ void __launch_bounds__(256, 1)
mma_gemm_proj(const float* __restrict__ bias, float* __restrict__ out)
{
    mma_gemm_body(g_c_hi, g_c_lo, g_Wp_hi, g_Wp_lo, bias, out, CDIM);
}

// ---------------- flash attention, fp32, BQ=BK=64, d=64 (unchanged, working) --------
constexpr int SROW = 68;

__global__ void __launch_bounds__(256)
flash_kernel(const int* __restrict__ mask)
{
    extern __shared__ float sm[];
    float* Qt = sm;
    float* Ks = sm + 64 * SROW;
    float* Vs = sm + 2 * 64 * SROW;

    const int tid = threadIdx.x;
    const int tx = tid & 15, ty = tid >> 4;
    const int b = blockIdx.z, h = blockIdx.y;
    const int q0 = blockIdx.x * 64;

    const float* Qg = g_qkv + (size_t)(b * NTOK + q0) * QKVC + h * HDIM;
#pragma unroll
    for (int i = 0; i < 4; i++) {
        int idx4 = tid + i * 256;
        int r  = idx4 >> 4;
        int d4 = (idx4 & 15) * 4;
        float4 v = *reinterpret_cast<const float4*>(Qg + (size_t)r * QKVC + d4);
        Qt[(d4 + 0) * SROW + r] = v.x;
        Qt[(d4 + 1) * SROW + r] = v.y;
        Qt[(d4 + 2) * SROW + r] = v.z;
        Qt[(d4 + 3) * SROW + r] = v.w;
    }

    float m_[4] = {-1e30f, -1e30f, -1e30f, -1e30f};
    float l_[4] = {0.f, 0.f, 0.f, 0.f};
    float o[4][4] = {};
    const int* mrow = mask + b * NTOK;

    for (int k0 = 0; k0 < NTOK; k0 += 64) {
        __syncthreads();
        const float* Kg = g_qkv + (size_t)(b * NTOK + k0) * QKVC + CDIM + h * HDIM;
#pragma unroll
        for (int i = 0; i < 4; i++) {
            int idx4 = tid + i * 256;
            int r  = idx4 >> 4;
            int d4 = (idx4 & 15) * 4;
            float4 kv = *reinterpret_cast<const float4*>(Kg + (size_t)r * QKVC + d4);
            Ks[(d4 + 0) * SROW + r] = kv.x;
            Ks[(d4 + 1) * SROW + r] = kv.y;
            Ks[(d4 + 2) * SROW + r] = kv.z;
            Ks[(d4 + 3) * SROW + r] = kv.w;
            float4 vv = *reinterpret_cast<const float4*>(Kg + CDIM + (size_t)r * QKVC + d4);
            *reinterpret_cast<float4*>(&Vs[r * SROW + d4]) = vv;
        }
        __syncthreads();

        float s[4][4] = {};
#pragma unroll 8
        for (int kk = 0; kk < 64; kk++) {
            float4 a  = *reinterpret_cast<const float4*>(&Qt[kk * SROW + ty * 4]);
            float4 bb = *reinterpret_cast<const float4*>(&Ks[kk * SROW + tx * 4]);
            float ar[4] = {a.x, a.y, a.z, a.w};
            float br[4] = {bb.x, bb.y, bb.z, bb.w};
#pragma unroll
            for (int i = 0; i < 4; i++)
#pragma unroll
                for (int j = 0; j < 4; j++) s[i][j] += ar[i] * br[j];
        }

        float msk[4];
#pragma unroll
        for (int j = 0; j < 4; j++)
            msk[j] = (mrow[k0 + tx * 4 + j] == 0) ? -1e30f : 0.0f;

#pragma unroll
        for (int i = 0; i < 4; i++) {
#pragma unroll
            for (int j = 0; j < 4; j++) s[i][j] = s[i][j] * 0.125f + msk[j];
            float pm = fmaxf(fmaxf(s[i][0], s[i][1]), fmaxf(s[i][2], s[i][3]));
#pragma unroll
            for (int off = 8; off; off >>= 1)
                pm = fmaxf(pm, __shfl_xor_sync(0xffffffffu, pm, off));
            float mn = fmaxf(m_[i], pm);
            float alpha = __expf(m_[i] - mn);
            m_[i] = mn;
            float ps = 0.f;
#pragma unroll
            for (int j = 0; j < 4; j++) {
                float p = __expf(s[i][j] - mn);
                s[i][j] = p;
                ps += p;
            }
#pragma unroll
            for (int off = 8; off; off >>= 1)
                ps += __shfl_xor_sync(0xffffffffu, ps, off);
            l_[i] = l_[i] * alpha + ps;
#pragma unroll
            for (int j = 0; j < 4; j++) o[i][j] *= alpha;
        }

        __syncthreads();
#pragma unroll
        for (int j = 0; j < 4; j++) {
            float4 pc = make_float4(s[0][j], s[1][j], s[2][j], s[3][j]);
            *reinterpret_cast<float4*>(&Ks[(tx * 4 + j) * SROW + ty * 4]) = pc;
        }
        __syncthreads();

#pragma unroll 8
        for (int kc = 0; kc < 64; kc++) {
            float4 a  = *reinterpret_cast<const float4*>(&Ks[kc * SROW + ty * 4]);
            float4 bv = *reinterpret_cast<const float4*>(&Vs[kc * SROW + tx * 4]);
            float ar[4] = {a.x, a.y, a.z, a.w};
            float br[4] = {bv.x, bv.y, bv.z, bv.w};
#pragma unroll
            for (int i = 0; i < 4; i++)
#pragma unroll
                for (int j = 0; j < 4; j++) o[i][j] += ar[i] * br[j];
        }
    }

#pragma unroll
    for (int i = 0; i < 4; i++) {
        float inv = 1.0f / l_[i];
        float4 r = make_float4(o[i][0] * inv, o[i][1] * inv, o[i][2] * inv, o[i][3] * inv);
        size_t row = (size_t)(b * NTOK + q0 + ty * 4 + i);
        *reinterpret_cast<float4*>(&g_ctx[row * CDIM + h * HDIM + tx * 4]) = r;
    }
}

// ---------------- launch ----------------
extern "C" void kernel_launch(void* const* d_in, const int* in_sizes, int n_in,
                              void* d_out, int out_size)
{
    (void)in_sizes; (void)n_in; (void)out_size;
    const float* x    = (const float*)d_in[0];
    const int*   mask = (const int*)d_in[1];
    const float* Wqkv = (const float*)d_in[2];
    const float* bqkv = (const float*)d_in[3];
    const float* Aqkv = (const float*)d_in[4];
    const float* Bqkv = (const float*)d_in[5];
    const float* Wp   = (const float*)d_in[6];
    const float* bp   = (const float*)d_in[7];
    const float* Ap   = (const float*)d_in[8];
    const float* Bp   = (const float*)d_in[9];
    float* out = (float*)d_out;

    // 1) fold LoRA into effective weights (bf16 hi/lo split) + split x
    fuse_qkv_kernel<<<(QKVC * CDIM + 255) / 256, 256>>>(Wqkv, Bqkv, Aqkv);
    fuse_p_kernel<<<(CDIM * CDIM + 255) / 256, 256>>>(Wp, Bp, Ap);
    cvt_x_kernel<<<(MROWS * CDIM + 255) / 256, 256>>>(x);

    // 2) qkv = x @ Weff_qkv^T + bqkv  (HMMA, split-bf16 3-term)
    cudaFuncSetAttribute(mma_gemm_qkv, cudaFuncAttributeMaxDynamicSharedMemorySize, GM_SMEM);
    mma_gemm_qkv<<<dim3(QKVC / 128, MROWS / 128), 256, GM_SMEM>>>(bqkv);

    // 3) flash attention -> g_ctx (fp32)
    int smem = 3 * 64 * SROW * (int)sizeof(float);   // 52224 B
    cudaFuncSetAttribute(flash_kernel, cudaFuncAttributeMaxDynamicSharedMemorySize, smem);
    flash_kernel<<<dim3(NTOK / 64, HEADS, BATCH), 256, smem>>>(mask);

    // 4) split ctx, then out = ctx @ Weff_p^T + bp (HMMA)
    cvt_ctx_kernel<<<(MROWS * CDIM + 255) / 256, 256>>>();
    cudaFuncSetAttribute(mma_gemm_proj, cudaFuncAttributeMaxDynamicSharedMemorySize, GM_SMEM);
    mma_gemm_proj<<<dim3(CDIM / 128, MROWS / 128), 256, GM_SMEM>>>(bp, out);
}

// round 7
// speedup vs baseline: 2.3662x; 1.8333x over previous
#include <cuda_runtime.h>
#include <cuda_bf16.h>
#include <cstdint>

// ---------------- problem constants ----------------
constexpr int BATCH = 2;
constexpr int NTOK  = 2048;
constexpr int CDIM  = 1024;
constexpr int HEADS = 16;
constexpr int HDIM  = 64;
constexpr int MROWS = BATCH * NTOK;     // 4096
constexpr int QKVC  = 3 * CDIM;         // 3072

// ---------------- scratch (device globals, no allocation) ----------------
__device__ __nv_bfloat16 g_x_hi[MROWS * CDIM];
__device__ __nv_bfloat16 g_x_lo[MROWS * CDIM];
__device__ __nv_bfloat16 g_Wq_hi[QKVC * CDIM];
__device__ __nv_bfloat16 g_Wq_lo[QKVC * CDIM];
__device__ __nv_bfloat16 g_Wp_hi[CDIM * CDIM];
__device__ __nv_bfloat16 g_Wp_lo[CDIM * CDIM];
// q/k/v in [B][H][N][64] bf16 hi/lo (written by qkv GEMM epilogue)
__device__ __nv_bfloat16 g_q_hi[MROWS * CDIM];
__device__ __nv_bfloat16 g_q_lo[MROWS * CDIM];
__device__ __nv_bfloat16 g_k_hi[MROWS * CDIM];
__device__ __nv_bfloat16 g_k_lo[MROWS * CDIM];
__device__ __nv_bfloat16 g_v_hi[MROWS * CDIM];
__device__ __nv_bfloat16 g_v_lo[MROWS * CDIM];
// ctx in [B][N][C] bf16 hi/lo (written by flash, read by proj GEMM)
__device__ __nv_bfloat16 g_c_hi[MROWS * CDIM];
__device__ __nv_bfloat16 g_c_lo[MROWS * CDIM];

// ---------------- helpers ----------------
__device__ __forceinline__ void split2(float v, __nv_bfloat16& h, __nv_bfloat16& l)
{
    h = __float2bfloat16_rn(v);
    l = __float2bfloat16_rn(v - __bfloat162float(h));
}

__device__ __forceinline__ uint32_t smem_u32(const void* p)
{
    uint32_t a;
    asm("{ .reg .u64 t; cvta.to.shared.u64 t, %1; cvt.u32.u64 %0, t; }" : "=r"(a) : "l"(p));
    return a;
}

__device__ __forceinline__ void cp_async16(uint32_t dst, const void* src)
{
    asm volatile("cp.async.cg.shared.global [%0], [%1], 16;" :: "r"(dst), "l"(src));
}

__device__ __forceinline__ void ldsm_x4(uint32_t& r0, uint32_t& r1, uint32_t& r2, uint32_t& r3,
                                        uint32_t addr)
{
    asm volatile("ldmatrix.sync.aligned.m8n8.x4.shared.b16 {%0,%1,%2,%3}, [%4];"
                 : "=r"(r0), "=r"(r1), "=r"(r2), "=r"(r3) : "r"(addr));
}

__device__ __forceinline__ void ldsm_x4_t(uint32_t& r0, uint32_t& r1, uint32_t& r2, uint32_t& r3,
                                          uint32_t addr)
{
    asm volatile("ldmatrix.sync.aligned.m8n8.x4.trans.shared.b16 {%0,%1,%2,%3}, [%4];"
                 : "=r"(r0), "=r"(r1), "=r"(r2), "=r"(r3) : "r"(addr));
}

__device__ __forceinline__ void mma_bf16(float* c, const uint32_t* a, const uint32_t* b)
{
    asm volatile("mma.sync.aligned.m16n8k16.row.col.f32.bf16.bf16.f32 "
                 "{%0,%1,%2,%3}, {%4,%5,%6,%7}, {%8,%9}, {%0,%1,%2,%3};"
                 : "+f"(c[0]), "+f"(c[1]), "+f"(c[2]), "+f"(c[3])
                 : "r"(a[0]), "r"(a[1]), "r"(a[2]), "r"(a[3]), "r"(b[0]), "r"(b[1]));
}

// ---------------- conversion kernel ----------------
__global__ void cvt_x_kernel(const float* __restrict__ x)
{
    int i = blockIdx.x * blockDim.x + threadIdx.x;
    if (i < MROWS * CDIM) split2(x[i], g_x_hi[i], g_x_lo[i]);
}

// ---------------- weight fusion + split: Weff = W + 2 * B @ A ----------------
__device__ __forceinline__ void fuse_body(const float* __restrict__ W,
                                          const float* __restrict__ Bm,
                                          const float* __restrict__ A,
                                          __nv_bfloat16* __restrict__ Whi,
                                          __nv_bfloat16* __restrict__ Wlo, int total)
{
    int idx = blockIdx.x * blockDim.x + threadIdx.x;
    if (idx >= total) return;
    int i = idx >> 10;
    int j = idx & 1023;
    float s = 0.f;
#pragma unroll
    for (int r = 0; r < 16; r++) s += Bm[i * 16 + r] * A[r * CDIM + j];
    split2(W[idx] + 2.0f * s, Whi[idx], Wlo[idx]);
}

__global__ void fuse_qkv_kernel(const float* __restrict__ W, const float* __restrict__ Bm,
                                const float* __restrict__ A)
{
    fuse_body(W, Bm, A, g_Wq_hi, g_Wq_lo, QKVC * CDIM);
}

__global__ void fuse_p_kernel(const float* __restrict__ W, const float* __restrict__ Bm,
                              const float* __restrict__ A)
{
    fuse_body(W, Bm, A, g_Wp_hi, g_Wp_lo, CDIM * CDIM);
}

// ---------------- HMMA GEMM (128x128 tile, 8 warps, 3-term split bf16) --------------
constexpr int GM_RS    = 80;
constexpr int GM_ARR   = 128 * GM_RS;        // 10240
constexpr int GM_STAGE = 4 * GM_ARR;         // 40960
constexpr int GM_SMEM  = 2 * GM_STAGE;       // 81920
constexpr int KCH      = 32;
constexpr int NCHUNK   = 1024 / KCH;         // 32

__device__ __forceinline__ void gm_load_chunk(uint32_t su, int tid,
                                              const __nv_bfloat16* const* srcs, int c)
{
    uint32_t stage = su + (uint32_t)(c & 1) * GM_STAGE;
    int k0 = c * KCH;
#pragma unroll
    for (int i = 0; i < 8; i++) {
        int g = i * 256 + tid;
        int t = g >> 9;
        int e = g & 511;
        int r = e >> 2;
        int c16 = e & 3;
        cp_async16(stage + t * GM_ARR + r * GM_RS + c16 * 16,
                   srcs[t] + (size_t)r * 1024 + k0 + c16 * 8);
    }
    asm volatile("cp.async.commit_group;");
}

template <bool QKV_SPLIT_OUT>
__device__ __forceinline__ void mma_gemm_body(const __nv_bfloat16* __restrict__ Ahi,
                                              const __nv_bfloat16* __restrict__ Alo,
                                              const __nv_bfloat16* __restrict__ Bhi,
                                              const __nv_bfloat16* __restrict__ Blo,
                                              const float* __restrict__ bias,
                                              float* __restrict__ C, int Nc)
{
    extern __shared__ char smem[];
    const uint32_t su = smem_u32(smem);
    const int tid = threadIdx.x;
    const int wid = tid >> 5, lane = tid & 31;
    const int warp_m = wid >> 2, warp_n = wid & 3;
    const int row0 = blockIdx.y * 128;
    const int col0 = blockIdx.x * 128;

    const __nv_bfloat16* srcs[4] = {
        Ahi + (size_t)row0 * 1024, Alo + (size_t)row0 * 1024,
        Bhi + (size_t)col0 * 1024, Blo + (size_t)col0 * 1024 };

    float acc[4][4][4];
#pragma unroll
    for (int mt = 0; mt < 4; mt++)
#pragma unroll
        for (int nt = 0; nt < 4; nt++)
#pragma unroll
            for (int f = 0; f < 4; f++) acc[mt][nt][f] = 0.f;

    gm_load_chunk(su, tid, srcs, 0);

    const int a_row = warp_m * 64 + (lane & 15);
    const int a_kb  = (lane >> 4) << 4;
    const int b_row = warp_n * 32 + ((lane & 7) | ((lane & 16) >> 1));
    const int b_kb  = (lane & 8) << 1;

    for (int c = 0; c < NCHUNK; c++) {
        if (c + 1 < NCHUNK) {
            __syncthreads();
            gm_load_chunk(su, tid, srcs, c + 1);
            asm volatile("cp.async.wait_group 1;" ::: "memory");
        } else {
            asm volatile("cp.async.wait_group 0;" ::: "memory");
        }
        __syncthreads();

        const uint32_t stage = su + (uint32_t)(c & 1) * GM_STAGE;
#pragma unroll
        for (int ks = 0; ks < 2; ks++) {
            const uint32_t koff = ks * 32;

            uint32_t ah[4][4], al[4][4];
#pragma unroll
            for (int mt = 0; mt < 4; mt++) {
                uint32_t base = (uint32_t)((a_row + mt * 16) * GM_RS + a_kb + koff);
                ldsm_x4(ah[mt][0], ah[mt][1], ah[mt][2], ah[mt][3], stage + 0 * GM_ARR + base);
                ldsm_x4(al[mt][0], al[mt][1], al[mt][2], al[mt][3], stage + 1 * GM_ARR + base);
            }
            uint32_t bh[4][2], bl[4][2];
#pragma unroll
            for (int np = 0; np < 2; np++) {
                uint32_t base = (uint32_t)((b_row + np * 16) * GM_RS + b_kb + koff);
                uint32_t r0, r1, r2, r3;
                ldsm_x4(r0, r1, r2, r3, stage + 2 * GM_ARR + base);
                bh[np * 2][0] = r0; bh[np * 2][1] = r1;
                bh[np * 2 + 1][0] = r2; bh[np * 2 + 1][1] = r3;
                ldsm_x4(r0, r1, r2, r3, stage + 3 * GM_ARR + base);
                bl[np * 2][0] = r0; bl[np * 2][1] = r1;
                bl[np * 2 + 1][0] = r2; bl[np * 2 + 1][1] = r3;
            }
#pragma unroll
            for (int mt = 0; mt < 4; mt++)
#pragma unroll
                for (int nt = 0; nt < 4; nt++) {
                    mma_bf16(acc[mt][nt], ah[mt], bh[nt]);
                    mma_bf16(acc[mt][nt], al[mt], bh[nt]);
                    mma_bf16(acc[mt][nt], ah[mt], bl[nt]);
                }
        }
    }

    if (!QKV_SPLIT_OUT) {
#pragma unroll
        for (int mt = 0; mt < 4; mt++) {
            int rg = row0 + warp_m * 64 + mt * 16 + (lane >> 2);
#pragma unroll
            for (int nt = 0; nt < 4; nt++) {
                int cg = col0 + warp_n * 32 + nt * 8 + (lane & 3) * 2;
                float b0 = bias[cg], b1 = bias[cg + 1];
                float2 v0 = make_float2(acc[mt][nt][0] + b0, acc[mt][nt][1] + b1);
                float2 v1 = make_float2(acc[mt][nt][2] + b0, acc[mt][nt][3] + b1);
                *reinterpret_cast<float2*>(&C[(size_t)rg * Nc + cg]) = v0;
                *reinterpret_cast<float2*>(&C[(size_t)(rg + 8) * Nc + cg]) = v1;
            }
        }
    } else {
        // scatter to q/k/v hi/lo in [B][H][N][64] layout
        __nv_bfloat162* hiA[3] = { reinterpret_cast<__nv_bfloat162*>(g_q_hi),
                                   reinterpret_cast<__nv_bfloat162*>(g_k_hi),
                                   reinterpret_cast<__nv_bfloat162*>(g_v_hi) };
        __nv_bfloat162* loA[3] = { reinterpret_cast<__nv_bfloat162*>(g_q_lo),
                                   reinterpret_cast<__nv_bfloat162*>(g_k_lo),
                                   reinterpret_cast<__nv_bfloat162*>(g_v_lo) };
#pragma unroll
        for (int nt = 0; nt < 4; nt++) {
            int cg = col0 + warp_n * 32 + nt * 8 + (lane & 3) * 2;
            int which = cg >> 10;
            int rem = cg & 1023;
            int h = rem >> 6;
            int d = rem & 63;
            float b0 = bias[cg], b1 = bias[cg + 1];
#pragma unroll
            for (int mt = 0; mt < 4; mt++) {
                int rbase = row0 + warp_m * 64 + mt * 16 + (lane >> 2);
#pragma unroll
                for (int half = 0; half < 2; half++) {
                    int r = rbase + half * 8;
                    int bb = r >> 11, n = r & 2047;
                    size_t di = (((size_t)((bb << 4) + h) * 2048 + n) * 64 + d) >> 1;
                    float v0 = acc[mt][nt][half * 2 + 0] + b0;
                    float v1 = acc[mt][nt][half * 2 + 1] + b1;
                    __nv_bfloat16 h0, l0, h1, l1;
                    split2(v0, h0, l0);
                    split2(v1, h1, l1);
                    hiA[which][di] = __nv_bfloat162(h0, h1);
                    loA[which][di] = __nv_bfloat162(l0, l1);
                }
            }
        }
    }
}

__global__ void __launch_bounds__(256, 1)
mma_gemm_qkv(const float* __restrict__ bias)
{
    mma_gemm_body<true>(g_x_hi, g_x_lo, g_Wq_hi, g_Wq_lo, bias, nullptr, QKVC);
}

__global__ void __launch_bounds__(256, 1)
mma_gemm_proj(const float* __restrict__ bias, float* __restrict__ out)
{
    mma_gemm_body<false>(g_c_hi, g_c_lo, g_Wp_hi, g_Wp_lo, bias, out, CDIM);
}

// ---------------- HMMA flash attention: BQ=128, BK=64, d=64, 8 warps ----------------
constexpr int FA_RS    = 144;               // 128B data + 16B pad
constexpr int FA_ARR   = 64 * FA_RS;        // 9216
constexpr int FA_STAGE = 4 * FA_ARR;        // 36864 (Khi|Klo|Vhi|Vlo)
constexpr int FA_MASK  = 2 * FA_STAGE;      // 73728
constexpr int FA_SMEM  = FA_MASK + 2 * 256; // 74240

__device__ __forceinline__ void fa_load_stage(uint32_t su, int tid,
                                              const __nv_bfloat16* Khi,
                                              const __nv_bfloat16* Klo,
                                              const __nv_bfloat16* Vhi,
                                              const __nv_bfloat16* Vlo,
                                              const int* msrc, int blk)
{
    const uint32_t sb = su + (uint32_t)(blk & 1) * FA_STAGE;
    const size_t off = (size_t)blk * 64 * 64;
    const __nv_bfloat16* srcs[4] = { Khi + off, Klo + off, Vhi + off, Vlo + off };
#pragma unroll
    for (int i = 0; i < 8; i++) {
        int g = i * 256 + tid;
        int arr = g >> 9;
        int e = g & 511;
        int r = e >> 3;
        int ch = e & 7;
        cp_async16(sb + arr * FA_ARR + r * FA_RS + ch * 16,
                   srcs[arr] + (size_t)r * 64 + ch * 8);
    }
    if (tid < 16)
        cp_async16(su + FA_MASK + (uint32_t)(blk & 1) * 256 + tid * 16,
                   msrc + blk * 64 + tid * 4);
    asm volatile("cp.async.commit_group;");
}

__global__ void __launch_bounds__(256)
flash_mma_kernel(const int* __restrict__ mask)
{
    extern __shared__ char smem[];
    const uint32_t su = smem_u32(smem);
    const int tid = threadIdx.x;
    const int wid = tid >> 5, lane = tid & 31;
    const int b = blockIdx.z, h = blockIdx.y;
    const int q0 = blockIdx.x * 128;
    const size_t bh = (size_t)(b * HEADS + h);

    const __nv_bfloat16* Qhi = g_q_hi + (bh * NTOK + q0) * 64;
    const __nv_bfloat16* Qlo = g_q_lo + (bh * NTOK + q0) * 64;
    const __nv_bfloat16* Khi = g_k_hi + bh * NTOK * 64;
    const __nv_bfloat16* Klo = g_k_lo + bh * NTOK * 64;
    const __nv_bfloat16* Vhi = g_v_hi + bh * NTOK * 64;
    const __nv_bfloat16* Vlo = g_v_lo + bh * NTOK * 64;
    const int* msrc = mask + b * NTOK;

    // ---- stage Q (128 rows x 64 bf16, hi+lo) into smem, then into registers ----
#pragma unroll
    for (int i = 0; i < 8; i++) {
        int g = i * 256 + tid;
        int arr = g >> 10;
        int e = g & 1023;
        int r = e >> 3;
        int ch = e & 7;
        cp_async16(su + arr * 18432 + r * FA_RS + ch * 16,
                   (arr ? Qlo : Qhi) + (size_t)r * 64 + ch * 8);
    }
    asm volatile("cp.async.commit_group;");
    asm volatile("cp.async.wait_group 0;" ::: "memory");
    __syncthreads();

    uint32_t qh[4][4], ql[4][4];
    {
        const int ar = wid * 16 + (lane & 15);
        const uint32_t ab = (uint32_t)((lane >> 4) << 4);
#pragma unroll
        for (int ks = 0; ks < 4; ks++) {
            uint32_t base = (uint32_t)(ar * FA_RS) + ab + ks * 32;
            ldsm_x4(qh[ks][0], qh[ks][1], qh[ks][2], qh[ks][3], su + base);
            ldsm_x4(ql[ks][0], ql[ks][1], ql[ks][2], ql[ks][3], su + 18432 + base);
        }
    }
    __syncthreads();

    float O[8][4];
#pragma unroll
    for (int t = 0; t < 8; t++)
#pragma unroll
        for (int f = 0; f < 4; f++) O[t][f] = 0.f;
    float m0 = -1e30f, m1 = -1e30f, l0 = 0.f, l1 = 0.f;

    fa_load_stage(su, tid, Khi, Klo, Vhi, Vlo, msrc, 0);

    const int kb_row = (lane & 7) | ((lane & 16) >> 1);     // K ldsm row-in-16
    const uint32_t kb_off = (uint32_t)((lane & 8) << 1);    // K ldsm 16B col
    const int v_row = lane & 15;                            // V ldsm row-in-16
    const uint32_t v_off = (uint32_t)(((lane & 16) >> 4) * 16);

    for (int blk = 0; blk < 32; blk++) {
        const int st = blk & 1;
        if (blk + 1 < 32) {
            fa_load_stage(su, tid, Khi, Klo, Vhi, Vlo, msrc, blk + 1);
            asm volatile("cp.async.wait_group 1;" ::: "memory");
        } else {
            asm volatile("cp.async.wait_group 0;" ::: "memory");
        }
        __syncthreads();

        const uint32_t sb = su + (uint32_t)st * FA_STAGE;

        // ---- S = Q K^T (3-term split) ----
        float S[8][4];
#pragma unroll
        for (int t = 0; t < 8; t++)
#pragma unroll
            for (int f = 0; f < 4; f++) S[t][f] = 0.f;

#pragma unroll
        for (int ks = 0; ks < 4; ks++) {
            uint32_t kh[4][4], kl[4][4];
#pragma unroll
            for (int np = 0; np < 4; np++) {
                uint32_t base = (uint32_t)((np * 16 + kb_row) * FA_RS) + kb_off + ks * 32;
                ldsm_x4(kh[np][0], kh[np][1], kh[np][2], kh[np][3], sb + 0 * FA_ARR + base);
                ldsm_x4(kl[np][0], kl[np][1], kl[np][2], kl[np][3], sb + 1 * FA_ARR + base);
            }
#pragma unroll
            for (int np = 0; np < 4; np++) {
                mma_bf16(S[2 * np],     qh[ks], &kh[np][0]);
                mma_bf16(S[2 * np + 1], qh[ks], &kh[np][2]);
            }
#pragma unroll
            for (int np = 0; np < 4; np++) {
                mma_bf16(S[2 * np],     ql[ks], &kh[np][0]);
                mma_bf16(S[2 * np + 1], ql[ks], &kh[np][2]);
            }
#pragma unroll
            for (int np = 0; np < 4; np++) {
                mma_bf16(S[2 * np],     qh[ks], &kl[np][0]);
                mma_bf16(S[2 * np + 1], qh[ks], &kl[np][2]);
            }
        }

        // ---- mask + online softmax ----
        const int* mrow = reinterpret_cast<const int*>(smem + FA_MASK + st * 256);
        float mx0 = -1e30f, mx1 = -1e30f;
#pragma unroll
        for (int t = 0; t < 8; t++) {
            int c0 = t * 8 + (lane & 3) * 2;
            float k0m = (mrow[c0] == 0) ? -1e30f : 0.f;
            float k1m = (mrow[c0 + 1] == 0) ? -1e30f : 0.f;
            S[t][0] = S[t][0] * 0.125f + k0m;
            S[t][1] = S[t][1] * 0.125f + k1m;
            S[t][2] = S[t][2] * 0.125f + k0m;
            S[t][3] = S[t][3] * 0.125f + k1m;
            mx0 = fmaxf(mx0, fmaxf(S[t][0], S[t][1]));
            mx1 = fmaxf(mx1, fmaxf(S[t][2], S[t][3]));
        }
#pragma unroll
        for (int off = 1; off <= 2; off <<= 1) {
            mx0 = fmaxf(mx0, __shfl_xor_sync(0xffffffffu, mx0, off));
            mx1 = fmaxf(mx1, __shfl_xor_sync(0xffffffffu, mx1, off));
        }
        float mn0 = fmaxf(m0, mx0), mn1 = fmaxf(m1, mx1);
        float al0 = __expf(m0 - mn0), al1 = __expf(m1 - mn1);
        m0 = mn0; m1 = mn1;
        float s0 = 0.f, s1 = 0.f;
#pragma unroll
        for (int t = 0; t < 8; t++) {
            S[t][0] = __expf(S[t][0] - mn0);
            S[t][1] = __expf(S[t][1] - mn0);
            S[t][2] = __expf(S[t][2] - mn1);
            S[t][3] = __expf(S[t][3] - mn1);
            s0 += S[t][0] + S[t][1];
            s1 += S[t][2] + S[t][3];
        }
#pragma unroll
        for (int off = 1; off <= 2; off <<= 1) {
            s0 += __shfl_xor_sync(0xffffffffu, s0, off);
            s1 += __shfl_xor_sync(0xffffffffu, s1, off);
        }
        l0 = l0 * al0 + s0;
        l1 = l1 * al1 + s1;
#pragma unroll
        for (int t = 0; t < 8; t++) {
            O[t][0] *= al0; O[t][1] *= al0;
            O[t][2] *= al1; O[t][3] *= al1;
        }

        // ---- pack P into hi/lo A-fragments ----
        uint32_t ph[4][4], pl[4][4];
#pragma unroll
        for (int s = 0; s < 4; s++) {
#pragma unroll
            for (int half = 0; half < 2; half++) {          // tile 2s, 2s+1 -> a0/a1, a2/a3
#pragma unroll
                for (int rr = 0; rr < 2; rr++) {            // rows r0 (c0,c1), r0+8 (c2,c3)
                    float p0 = S[2 * s + half][rr * 2 + 0];
                    float p1 = S[2 * s + half][rr * 2 + 1];
                    __nv_bfloat16 h0, lo0, h1, lo1;
                    split2(p0, h0, lo0);
                    split2(p1, h1, lo1);
                    int ri = half * 2 + rr;
                    __nv_bfloat162 vh(h0, h1), vl(lo0, lo1);
                    ph[s][ri] = *reinterpret_cast<uint32_t*>(&vh);
                    pl[s][ri] = *reinterpret_cast<uint32_t*>(&vl);
                }
            }
        }

        // ---- O += P V (3-term split) ----
#pragma unroll
        for (int s = 0; s < 4; s++) {
            uint32_t vh[4][4], vl[4][4];
#pragma unroll
            for (int np = 0; np < 4; np++) {
                uint32_t base = (uint32_t)((16 * s + v_row) * FA_RS) + np * 32 + v_off;
                ldsm_x4_t(vh[np][0], vh[np][1], vh[np][2], vh[np][3], sb + 2 * FA_ARR + base);
                ldsm_x4_t(vl[np][0], vl[np][1], vl[np][2], vl[np][3], sb + 3 * FA_ARR + base);
            }
#pragma unroll
            for (int np = 0; np < 4; np++) {
                mma_bf16(O[2 * np],     ph[s], &vh[np][0]);
                mma_bf16(O[2 * np + 1], ph[s], &vh[np][2]);
            }
#pragma unroll
            for (int np = 0; np < 4; np++) {
                mma_bf16(O[2 * np],     pl[s], &vh[np][0]);
                mma_bf16(O[2 * np + 1], pl[s], &vh[np][2]);
            }
#pragma unroll
            for (int np = 0; np < 4; np++) {
                mma_bf16(O[2 * np],     ph[s], &vl[np][0]);
                mma_bf16(O[2 * np + 1], ph[s], &vl[np][2]);
            }
        }
        __syncthreads();
    }

    // ---- normalize, split, write ctx [B][N][C] hi/lo ----
    const float inv0 = 1.0f / l0, inv1 = 1.0f / l1;
    const int r0 = q0 + wid * 16 + (lane >> 2);
    __nv_bfloat162* chi = reinterpret_cast<__nv_bfloat162*>(g_c_hi);
    __nv_bfloat162* clo = reinterpret_cast<__nv_bfloat162*>(g_c_lo);
#pragma unroll
    for (int t = 0; t < 8; t++) {
        int d = t * 8 + (lane & 3) * 2;
        size_t di0 = (((size_t)(b * NTOK + r0) * CDIM) + h * 64 + d) >> 1;
        size_t di1 = (((size_t)(b * NTOK + r0 + 8) * CDIM) + h * 64 + d) >> 1;
        float v0 = O[t][0] * inv0, v1 = O[t][1] * inv0;
        float v2 = O[t][2] * inv1, v3 = O[t][3] * inv1;
        __nv_bfloat16 h0, lo0, h1, lo1;
        split2(v0, h0, lo0); split2(v1, h1, lo1);
        chi[di0] = __nv_bfloat162(h0, h1);
        clo[di0] = __nv_bfloat162(lo0, lo1);
        split2(v2, h0, lo0); split2(v3, h1, lo1);
        chi[di1] = __nv_bfloat162(h0, h1);
        clo[di1] = __nv_bfloat162(lo0, lo1);
    }
}

// ---------------- launch ----------------
extern "C" void kernel_launch(void* const* d_in, const int* in_sizes, int n_in,
                              void* d_out, int out_size)
{
    (void)in_sizes; (void)n_in; (void)out_size;
    const float* x    = (const float*)d_in[0];
    const int*   mask = (const int*)d_in[1];
    const float* Wqkv = (const float*)d_in[2];
    const float* bqkv = (const float*)d_in[3];
    const float* Aqkv = (const float*)d_in[4];
    const float* Bqkv = (const float*)d_in[5];
    const float* Wp   = (const float*)d_in[6];
    const float* bp   = (const float*)d_in[7];
    const float* Ap   = (const float*)d_in[8];
    const float* Bp   = (const float*)d_in[9];
    float* out = (float*)d_out;

    // 1) fold LoRA into effective weights (bf16 hi/lo split) + split x
    fuse_qkv_kernel<<<(QKVC * CDIM + 255) / 256, 256>>>(Wqkv, Bqkv, Aqkv);
    fuse_p_kernel<<<(CDIM * CDIM + 255) / 256, 256>>>(Wp, Bp, Ap);
    cvt_x_kernel<<<(MROWS * CDIM + 255) / 256, 256>>>(x);

    // 2) qkv GEMM -> split q/k/v bf16 [B,H,N,d]
    cudaFuncSetAttribute(mma_gemm_qkv, cudaFuncAttributeMaxDynamicSharedMemorySize, GM_SMEM);
    mma_gemm_qkv<<<dim3(QKVC / 128, MROWS / 128), 256, GM_SMEM>>>(bqkv);

    // 3) HMMA flash attention -> ctx hi/lo
    cudaFuncSetAttribute(flash_mma_kernel, cudaFuncAttributeMaxDynamicSharedMemorySize, FA_SMEM);
    flash_mma_kernel<<<dim3(NTOK / 128, HEADS, BATCH), 256, FA_SMEM>>>(mask);

    // 4) proj GEMM -> out f32
    cudaFuncSetAttribute(mma_gemm_proj, cudaFuncAttributeMaxDynamicSharedMemorySize, GM_SMEM);
    mma_gemm_proj<<<dim3(CDIM / 128, MROWS / 128), 256, GM_SMEM>>>(bp, out);
}